// round 3
// baseline (speedup 1.0000x reference)
#include <cuda_runtime.h>
#include <stdint.h>

#define NB 4          // batch
#define MB 50         // gt boxes per batch
#define KB 240000     // anchors
#define NK (NB*KB)
#define SELK 256      // NUM_FG == NUM_BG
#define NBINS 4096    // 12-bit first-stage radix
#define CAP 8192      // candidate buffer per selection

// ---------------- persistent scratch (no allocations allowed) ----------------
__device__ uint8_t      g_flags[NK];          // 0 none, 1 pos, 2 neg
__device__ unsigned int g_hist[8][NBINS];     // zero-init; cleared by at_mid last block each replay
__device__ unsigned int g_prefix[8];
__device__ int          g_kk[8];
__device__ int          g_done[8];
__device__ unsigned int g_thresh[8];
__device__ unsigned int g_cnt[8];             // cleared by at_mid last block
__device__ unsigned int g_cand[8][CAP];
__device__ unsigned int g_tick1, g_tick2;     // ticket counters (self-resetting)

__device__ __forceinline__ unsigned int fkey(float f) {
    unsigned int u = __float_as_uint(f);
    return (u & 0x80000000u) ? ~u : (u | 0x80000000u);  // order-preserving
}

// Block-cooperative (256 threads): find bin b (scanning from the TOP) such that the
// cumulative count of bins > b is < kk and including bin b is >= kk.
// Writes s_out[0]=bin, s_out[1]=kk-(count strictly above bin), s_out[2]=total.
// If total < kk, s_out[0..1] are untouched. nbins must be a multiple of 256.
__device__ void topbin256(const unsigned int* hist, int nbins, unsigned int kk,
                          unsigned int* s_chunk, unsigned int* s_out) {
    const int t = threadIdx.x;
    const int per = nbins >> 8;
    const int base = t * per;
    unsigned int sum = 0;
    #pragma unroll 4
    for (int i = 0; i < per; ++i) sum += hist[base + i];
    s_chunk[t] = sum;
    __syncthreads();
    // inclusive suffix scan: s_chunk[t] = sum over chunks u >= t
    for (int off = 1; off < 256; off <<= 1) {
        unsigned int v = (t + off < 256) ? s_chunk[t + off] : 0u;
        __syncthreads();
        s_chunk[t] += v;
        __syncthreads();
    }
    if (t == 0) s_out[2] = s_chunk[0];
    const unsigned int above = s_chunk[t] - sum;   // strictly above this chunk
    if (above < kk && above + sum >= kk) {         // exactly one thread
        unsigned int cum = above;
        for (int b = per - 1; b >= 0; --b) {
            unsigned int c = hist[base + b];
            if (cum + c >= kk) { s_out[0] = (unsigned int)(base + b); s_out[1] = kk - cum; break; }
            cum += c;
        }
    }
    __syncthreads();
}

// ---------------- main: IoU max/argmax, targets, flags, fused hist; last block = scanA ----
__global__ void __launch_bounds__(256) at_main_kernel(
        const float4* __restrict__ anchors,
        const float4* __restrict__ gt_boxes,
        const int*    __restrict__ gt_labels,
        const float*  __restrict__ scores,
        float*        __restrict__ out) {
    __shared__ float4 s_gt[MB];
    __shared__ float  s_area[MB];
    __shared__ float  s_lab[MB];
    __shared__ unsigned int s_chunk[256];
    __shared__ unsigned int s_out[3];
    __shared__ int s_last;

    const int n = blockIdx.y;
    for (int i = threadIdx.x; i < MB; i += blockDim.x) {
        float4 g = gt_boxes[n * MB + i];
        s_gt[i]   = g;
        s_area[i] = __fmul_rn(__fsub_rn(g.z, g.x), __fsub_rn(g.w, g.y));
        s_lab[i]  = (float)gt_labels[n * MB + i];
    }
    __syncthreads();

    const int k = blockIdx.x * blockDim.x + threadIdx.x;
    if (k < KB) {
        float4 a = anchors[k];
        float area_a = __fmul_rn(__fsub_rn(a.z, a.x), __fsub_rn(a.w, a.y));
        float aw  = a.z - a.x,        ah  = a.w - a.y;
        float acx = a.x + 0.5f * aw,  acy = a.y + 0.5f * ah;

        float best_i, best_d; int best_m = 0;
        {
            float4 g = s_gt[0];
            float w = fmaxf(__fsub_rn(fminf(a.z, g.z), fmaxf(a.x, g.x)), 0.f);
            float h = fmaxf(__fsub_rn(fminf(a.w, g.w), fmaxf(a.y, g.y)), 0.f);
            best_i = __fmul_rn(w, h);
            best_d = __fadd_rn(__fsub_rn(__fadd_rn(area_a, s_area[0]), best_i), 1e-8f);
        }
        #pragma unroll 7
        for (int m = 1; m < MB; ++m) {
            float4 g = s_gt[m];
            float w = fmaxf(__fsub_rn(fminf(a.z, g.z), fmaxf(a.x, g.x)), 0.f);
            float h = fmaxf(__fsub_rn(fminf(a.w, g.w), fmaxf(a.y, g.y)), 0.f);
            float inter = __fmul_rn(w, h);
            float denom = __fadd_rn(__fsub_rn(__fadd_rn(area_a, s_area[m]), inter), 1e-8f);
            // division-free compare: inter/denom > best_i/best_d <=> inter*best_d > best_i*denom
            float lhs  = __fmul_rn(inter, best_d);
            float rhs  = __fmul_rn(best_i, denom);
            float diff = lhs - rhs;
            float mx   = fmaxf(lhs, rhs);
            bool better;
            if (fabsf(diff) <= 5e-6f * mx && mx > 0.f) {
                better = __fdiv_rn(inter, denom) > __fdiv_rn(best_i, best_d);  // rare exact path
            } else {
                better = diff > 0.f;
            }
            if (better) { best_i = inter; best_d = denom; best_m = m; }
        }

        bool pos, neg;
        {
            float t7 = __fmul_rn(0.7f, best_d);
            float d7 = __fsub_rn(best_i, t7);
            if (fabsf(d7) <= 5e-6f * t7) pos = (__fdiv_rn(best_i, best_d) >= 0.7f);
            else                          pos = (d7 >= 0.f);
            float t3 = __fmul_rn(0.3f, best_d);
            float d3 = __fsub_rn(best_i, t3);
            if (fabsf(d3) <= 5e-6f * t3) neg = (__fdiv_rn(best_i, best_d) < 0.3f);
            else                          neg = (d3 < 0.f);
        }

        const int idx = n * KB + k;
        uint8_t f = pos ? (uint8_t)1 : (neg ? (uint8_t)2 : (uint8_t)0);
        g_flags[idx] = f;
        out[idx] = pos ? s_lab[best_m] : 0.f;

        float4 r = make_float4(0.f, 0.f, 0.f, 0.f);
        if (pos) {  // rare: whole warps usually skip
            float4 g  = s_gt[best_m];
            float gw  = g.z - g.x,       gh  = g.w - g.y;
            float gcx = g.x + 0.5f * gw, gcy = g.y + 0.5f * gh;
            r.x = (gcx - acx) / aw;
            r.y = (gcy - acy) / ah;
            r.z = logf(gw / aw);
            r.w = logf(gh / ah);
        }
        ((float4*)(out + NK))[idx] = r;

        if (f) {  // fused 12-bit radix histogram (top 12 key bits)
            unsigned int key = fkey(scores[idx]);
            atomicAdd(&g_hist[n * 2 + (int)(f - 1)][key >> 20], 1u);
        }
    }

    // ----- ticket: last block to finish runs scanA inline -----
    __threadfence();
    __syncthreads();
    if (threadIdx.x == 0) {
        unsigned int old = atomicAdd(&g_tick1, 1u);
        s_last = (old == gridDim.x * gridDim.y - 1u);
    }
    __syncthreads();
    if (!s_last) return;
    __threadfence();

    for (int sel = 0; sel < 8; ++sel) {
        topbin256(g_hist[sel], NBINS, SELK, s_chunk, s_out);
        if (threadIdx.x == 0) {
            unsigned int total = s_out[2];
            if (total < SELK) { g_done[sel] = 1; g_thresh[sel] = 0u; }
            else { g_done[sel] = 0; g_prefix[sel] = s_out[0]; g_kk[sel] = (int)s_out[1]; }
        }
        __syncthreads();
    }
    if (threadIdx.x == 0) g_tick1 = 0u;
}

// ---------------- mid: gather candidates; last block = scanB + cleanup ----------------
__global__ void __launch_bounds__(256) at_mid_kernel(const float* __restrict__ scores) {
    __shared__ unsigned int s_chunk[256];
    __shared__ unsigned int s_out[3];
    __shared__ unsigned int s_hist[1024];
    __shared__ int s_last;

    const int n = blockIdx.y;
    const int selbase = n * 2;
    const int k = blockIdx.x * blockDim.x + threadIdx.x;

    const int d0 = g_done[selbase], d1 = g_done[selbase + 1];
    const unsigned int p0 = g_prefix[selbase], p1 = g_prefix[selbase + 1];

    if (k < KB && !(d0 && d1)) {
        const int idx = n * KB + k;
        uint8_t f = g_flags[idx];
        if (f) {
            int s = (int)f - 1;                     // 0 pos, 1 neg
            int done = s ? d1 : d0;
            unsigned int pfx = s ? p1 : p0;
            if (!done) {
                unsigned int key = fkey(scores[idx]);
                if ((key >> 20) == pfx) {
                    unsigned int slot = atomicAdd(&g_cnt[selbase + s], 1u);
                    if (slot < CAP) g_cand[selbase + s][slot] = key;
                }
            }
        }
    }

    __threadfence();
    __syncthreads();
    if (threadIdx.x == 0) {
        unsigned int old = atomicAdd(&g_tick2, 1u);
        s_last = (old == gridDim.x * gridDim.y - 1u);
    }
    __syncthreads();
    if (!s_last) return;
    __threadfence();

    for (int sel = 0; sel < 8; ++sel) {
        if (g_done[sel]) continue;
        const unsigned int kk = (unsigned int)g_kk[sel];
        const int c = (int)min(g_cnt[sel], (unsigned int)CAP);

        // pass 1: bits [10,20)
        for (int i = threadIdx.x; i < 1024; i += 256) s_hist[i] = 0u;
        __syncthreads();
        for (int i = threadIdx.x; i < c; i += 256)
            atomicAdd(&s_hist[(g_cand[sel][i] >> 10) & 1023u], 1u);
        __syncthreads();
        topbin256(s_hist, 1024, kk, s_chunk, s_out);
        const unsigned int b1 = s_out[0];
        const unsigned int k2 = s_out[1];
        __syncthreads();

        // pass 2: bits [0,10) among candidates in bin b1
        for (int i = threadIdx.x; i < 1024; i += 256) s_hist[i] = 0u;
        __syncthreads();
        for (int i = threadIdx.x; i < c; i += 256) {
            unsigned int key = g_cand[sel][i];
            if (((key >> 10) & 1023u) == b1) atomicAdd(&s_hist[key & 1023u], 1u);
        }
        __syncthreads();
        topbin256(s_hist, 1024, k2, s_chunk, s_out);
        if (threadIdx.x == 0)
            g_thresh[sel] = (g_prefix[sel] << 20) | (b1 << 10) | s_out[0];
        __syncthreads();
    }

    // cleanup for next graph replay
    for (int i = threadIdx.x; i < 8 * NBINS; i += 256) ((unsigned int*)g_hist)[i] = 0u;
    if (threadIdx.x < 8) g_cnt[threadIdx.x] = 0u;
    if (threadIdx.x == 0) g_tick2 = 0u;
}

// ---------------- finalize: weights = subsample mask ----------------
__global__ void __launch_bounds__(256) at_final_kernel(const float* __restrict__ scores,
                                                       float* __restrict__ out) {
    const int n = blockIdx.y;
    const int k = blockIdx.x * blockDim.x + threadIdx.x;
    if (k >= KB) return;
    const int idx = n * KB + k;
    uint8_t f = g_flags[idx];
    float cw = 0.f, rw = 0.f;
    if (f) {
        unsigned int key = fkey(scores[idx]);
        int sel = n * 2 + (int)(f - 1);
        if (key >= g_thresh[sel]) {
            cw = 1.f;
            rw = (f == 1) ? 1.f : 0.f;
        }
    }
    out[5 * NK + idx] = cw;
    out[6 * NK + idx] = rw;
}

// ---------------- launch ----------------
extern "C" void kernel_launch(void* const* d_in, const int* in_sizes, int n_in,
                              void* d_out, int out_size) {
    const float4* anchors  = (const float4*)d_in[0];   // (K,4) f32
    const float*  scores   = (const float*) d_in[1];   // (N,K) f32
    const float4* gt_boxes = (const float4*)d_in[2];   // (N,M,4) f32
    const int*    gt_lab   = (const int*)   d_in[3];   // (N,M) i32
    float* out = (float*)d_out;  // [cls_t | reg_t | cls_w | reg_w]

    const int GB = (KB + 255) / 256;   // 938
    at_main_kernel <<<dim3(GB, NB), 256>>>(anchors, gt_boxes, gt_lab, scores, out);
    at_mid_kernel  <<<dim3(GB, NB), 256>>>(scores);
    at_final_kernel<<<dim3(GB, NB), 256>>>(scores, out);
}

// round 4
// speedup vs baseline: 1.1915x; 1.1915x over previous
#include <cuda_runtime.h>
#include <stdint.h>

#define NB 4          // batch
#define MB 50         // gt boxes per batch
#define KB 240000     // anchors
#define NK (NB*KB)
#define SELK 256      // NUM_FG == NUM_BG
#define CAP 65536     // candidate buffer capacity per selection

// ---------------- persistent scratch (no allocations allowed) ----------------
__device__ uint8_t      g_flags[NK];          // 0 none, 1 pos, 2 neg
__device__ unsigned int g_hist[8][65536];     // 16-bit radix histograms (zero-init; cleared by at_final)
__device__ unsigned int g_prefix[8];
__device__ int          g_kk[8];
__device__ int          g_done[8];
__device__ unsigned int g_thresh[8];
__device__ unsigned int g_cnt[8];             // cleared by at_final
__device__ unsigned int g_cand[8][CAP];

__device__ __forceinline__ unsigned int fkey(float f) {
    unsigned int u = __float_as_uint(f);
    return (u & 0x80000000u) ? ~u : (u | 0x80000000u);  // order-preserving
}

// ---------------- main: IoU max/argmax, targets, flags, fused histogram ----------------
__global__ void __launch_bounds__(256) at_main_kernel(
        const float4* __restrict__ anchors,
        const float4* __restrict__ gt_boxes,
        const int*    __restrict__ gt_labels,
        const float*  __restrict__ scores,
        float*        __restrict__ out) {
    __shared__ float4 s_gt[MB];
    __shared__ float  s_S[MB];    // area_g + 1e-8  (fast-path S component)
    __shared__ float  s_ag[MB];   // raw area_g     (exact-path)
    __shared__ float  s_lab[MB];
    const int n = blockIdx.y;
    if (threadIdx.x < MB) {
        const int i = threadIdx.x;
        float4 g = gt_boxes[n * MB + i];
        s_gt[i]  = g;
        float ag = __fmul_rn(__fsub_rn(g.z, g.x), __fsub_rn(g.w, g.y));
        s_ag[i]  = ag;
        s_S[i]   = __fadd_rn(ag, 1e-8f);
        s_lab[i] = (float)gt_labels[n * MB + i];
    }
    __syncthreads();

    const int k = blockIdx.x * 256 + threadIdx.x;
    if (k >= KB) return;

    const float4 a = anchors[k];
    const float area_a = __fmul_rn(__fsub_rn(a.z, a.x), __fsub_rn(a.w, a.y));
    const float aw  = a.z - a.x,        ah  = a.w - a.y;
    const float acx = a.x + 0.5f * aw,  acy = a.y + 0.5f * ah;

    // ---- branchless fast loop: argmax of inter/S (monotone-equivalent to IoU) ----
    float best_i, best_S; int best_m = 0;
    bool bord = false;
    {
        float4 g = s_gt[0];
        float w = fmaxf(__fsub_rn(fminf(a.z, g.z), fmaxf(a.x, g.x)), 0.f);
        float h = fmaxf(__fsub_rn(fminf(a.w, g.w), fmaxf(a.y, g.y)), 0.f);
        best_i = __fmul_rn(w, h);
        best_S = area_a + s_S[0];
    }
    #pragma unroll 7
    for (int m = 1; m < MB; ++m) {
        float4 g = s_gt[m];
        float w = fmaxf(__fsub_rn(fminf(a.z, g.z), fmaxf(a.x, g.x)), 0.f);
        float h = fmaxf(__fsub_rn(fminf(a.w, g.w), fmaxf(a.y, g.y)), 0.f);
        float inter = __fmul_rn(w, h);
        float S     = area_a + s_S[m];
        float lhs   = __fmul_rn(inter, best_S);
        float rhs   = __fmul_rn(best_i, S);
        float mx     = fmaxf(lhs, rhs);
        float margin = fabsf(lhs - rhs) - 5e-6f * mx;
        bord |= (margin <= 0.f) & (mx > 0.f);     // near-tie: defer to exact redo
        bool better = lhs > rhs;
        best_i = better ? inter : best_i;
        best_S = better ? S     : best_S;
        best_m = better ? m     : best_m;
    }

    // ---- exact epilogue (reference rounding) ----
    float denom;
    if (__builtin_expect(bord, 0)) {
        // rare: redo everything with exact fp32 divisions, reference op order
        float biou = -1.f, bi = 0.f, bden = 1.f; int bm = 0;
        for (int m = 0; m < MB; ++m) {
            float4 g = s_gt[m];
            float w = fmaxf(__fsub_rn(fminf(a.z, g.z), fmaxf(a.x, g.x)), 0.f);
            float h = fmaxf(__fsub_rn(fminf(a.w, g.w), fmaxf(a.y, g.y)), 0.f);
            float inter = __fmul_rn(w, h);
            float den = __fadd_rn(__fsub_rn(__fadd_rn(area_a, s_ag[m]), inter), 1e-8f);
            float io  = __fdiv_rn(inter, den);
            if (io > biou) { biou = io; bm = m; bi = inter; bden = den; }
        }
        best_m = bm; best_i = bi; denom = bden;
    } else {
        denom = __fadd_rn(__fsub_rn(__fadd_rn(area_a, s_ag[best_m]), best_i), 1e-8f);
    }
    const float iou = __fdiv_rn(best_i, denom);   // exact reference max IoU
    const bool pos = iou >= 0.7f;
    const bool neg = iou <  0.3f;

    const int idx = n * KB + k;
    const uint8_t f = pos ? (uint8_t)1 : (neg ? (uint8_t)2 : (uint8_t)0);
    g_flags[idx] = f;
    out[idx] = pos ? s_lab[best_m] : 0.f;

    float4 r = make_float4(0.f, 0.f, 0.f, 0.f);
    if (pos) {  // rare: whole warps usually skip
        float4 g  = s_gt[best_m];
        float gw  = g.z - g.x,       gh  = g.w - g.y;
        float gcx = g.x + 0.5f * gw, gcy = g.y + 0.5f * gh;
        r.x = (gcx - acx) / aw;
        r.y = (gcy - acy) / ah;
        r.z = logf(gw / aw);
        r.w = logf(gh / ah);
    }
    ((float4*)(out + NK))[idx] = r;

    // fused 16-bit radix histogram (top 16 key bits)
    const float sc = __ldg(&scores[idx]);
    if (f) atomicAdd(&g_hist[n * 2 + (int)(f - 1)][fkey(sc) >> 16], 1u);
}

// ---------------- parallel suffix scan over 65536 bins per selection ----------------
__global__ void at_scanA_kernel() {
    const int sel = blockIdx.x;
    const int t   = threadIdx.x;           // 1024 threads, 64 bins each
    const unsigned int* __restrict__ h = g_hist[sel];
    __shared__ unsigned int s[1024];

    const int base = t * 64;
    unsigned int sum = 0;
    #pragma unroll 8
    for (int i = 0; i < 64; ++i) sum += h[base + i];
    s[t] = sum;
    __syncthreads();
    for (int off = 1; off < 1024; off <<= 1) {   // inclusive suffix scan
        unsigned int v = (t + off < 1024) ? s[t + off] : 0u;
        __syncthreads();
        s[t] += v;
        __syncthreads();
    }
    const unsigned int total = s[0];
    const unsigned int above = s[t] - sum;       // strictly above this chunk
    const unsigned int kk = SELK;

    if (t == 0) {
        g_done[sel] = (total < kk);
        if (total < kk) g_thresh[sel] = 0u;      // take all members
    }
    if (total >= kk && above < kk && above + sum >= kk) {   // exactly one thread
        unsigned int cum = above;
        for (int b = 63; b >= 0; --b) {
            unsigned int c = h[base + b];
            if (cum + c >= kk) {
                g_prefix[sel] = (unsigned int)(base + b);
                g_kk[sel]     = (int)(kk - cum);
                break;
            }
            cum += c;
        }
    }
}

// ---------------- collect candidates sharing the chosen 16-bit prefix ----------------
__global__ void at_collect_kernel(const float* __restrict__ scores) {
    const int sel = blockIdx.y;
    if (g_done[sel]) return;
    const int n = sel >> 1;
    const uint8_t want = (uint8_t)((sel & 1) + 1);
    const unsigned int pfx = g_prefix[sel];

    int k = blockIdx.x * blockDim.x + threadIdx.x;
    if (k >= KB) return;
    int idx = n * KB + k;
    if (g_flags[idx] != want) return;
    unsigned int key = fkey(scores[idx]);
    if ((key >> 16) != pfx) return;
    unsigned int slot = atomicAdd(&g_cnt[sel], 1u);
    if (slot < CAP) g_cand[sel][slot] = key;
}

// ---------------- exact low-16-bit selection among candidates ----------------
__global__ void at_scanB_kernel() {
    const int sel = blockIdx.x;
    if (g_done[sel]) return;
    const int t = threadIdx.x;              // 256 threads
    __shared__ unsigned int hist[256];
    __shared__ unsigned int s_b1, s_k2;

    const int c = (int)min(g_cnt[sel], (unsigned int)CAP);
    const unsigned int kk = (unsigned int)g_kk[sel];

    hist[t] = 0; __syncthreads();
    for (int i = t; i < c; i += 256)
        atomicAdd(&hist[(g_cand[sel][i] >> 8) & 255u], 1u);
    __syncthreads();
    if (t == 0) {
        unsigned int cum = 0;
        for (int b = 255; b >= 0; --b) {
            unsigned int h = hist[b];
            if (cum + h >= kk) { s_b1 = (unsigned int)b; s_k2 = kk - cum; break; }
            cum += h;
        }
    }
    __syncthreads();
    const unsigned int b1 = s_b1, k2 = s_k2;
    hist[t] = 0; __syncthreads();
    for (int i = t; i < c; i += 256) {
        unsigned int key = g_cand[sel][i];
        if (((key >> 8) & 255u) == b1) atomicAdd(&hist[key & 255u], 1u);
    }
    __syncthreads();
    if (t == 0) {
        unsigned int cum = 0;
        for (int b = 255; b >= 0; --b) {
            unsigned int h = hist[b];
            if (cum + h >= k2) {
                g_thresh[sel] = (g_prefix[sel] << 16) | (b1 << 8) | (unsigned int)b;
                break;
            }
            cum += h;
        }
    }
}

// ---------------- finalize weights + clear state for next replay ----------------
__global__ void __launch_bounds__(256) at_final_kernel(const float* __restrict__ scores,
                                                       float* __restrict__ out) {
    // clear hist/cnt for the next graph replay (first call relies on zero-init)
    unsigned int gid = (blockIdx.y * gridDim.x + blockIdx.x) * blockDim.x + threadIdx.x;
    if (gid < 8u * 65536u) ((unsigned int*)g_hist)[gid] = 0u;
    if (gid < 8u) g_cnt[gid] = 0u;

    const int n = blockIdx.y;
    int k = blockIdx.x * blockDim.x + threadIdx.x;
    if (k >= KB) return;
    int idx = n * KB + k;
    uint8_t f = g_flags[idx];
    float cw = 0.f, rw = 0.f;
    if (f) {
        unsigned int key = fkey(scores[idx]);
        int sel = n * 2 + (int)(f - 1);
        if (key >= g_thresh[sel]) {
            cw = 1.f;
            rw = (f == 1) ? 1.f : 0.f;
        }
    }
    out[5 * NK + idx] = cw;
    out[6 * NK + idx] = rw;
}

// ---------------- launch ----------------
extern "C" void kernel_launch(void* const* d_in, const int* in_sizes, int n_in,
                              void* d_out, int out_size) {
    const float4* anchors  = (const float4*)d_in[0];   // (K,4) f32
    const float*  scores   = (const float*) d_in[1];   // (N,K) f32
    const float4* gt_boxes = (const float4*)d_in[2];   // (N,M,4) f32
    const int*    gt_lab   = (const int*)   d_in[3];   // (N,M) i32
    float* out = (float*)d_out;  // [cls_t | reg_t | cls_w | reg_w]

    const int GB = (KB + 255) / 256;   // 938
    at_main_kernel   <<<dim3(GB, NB), 256>>>(anchors, gt_boxes, gt_lab, scores, out);
    at_scanA_kernel  <<<8, 1024>>>();
    at_collect_kernel<<<dim3(GB, 8), 256>>>(scores);
    at_scanB_kernel  <<<8, 256>>>();
    at_final_kernel  <<<dim3(GB, NB), 256>>>(scores, out);
}